// round 3
// baseline (speedup 1.0000x reference)
#include <cuda_runtime.h>

#define W       256
#define IMGPIX  65536
#define OW      246
#define STRIP   44
#define NSTRIPS 6
#define HSTR    130   // half-array row stride in float2 (128 cols + 2 pad)

__device__ float d_partials[3072];
__device__ int   d_count = 0;

typedef unsigned long long u64;

__device__ __forceinline__ u64 pk2(float a, float b) {
    u64 r;
    asm("mov.b64 %0, {%1, %2};" : "=l"(r) : "f"(a), "f"(b));
    return r;
}
__device__ __forceinline__ void upk2(u64 p, float& a, float& b) {
    asm("mov.b64 {%0, %1}, %2;" : "=f"(a), "=f"(b) : "l"(p));
}
__device__ __forceinline__ u64 fma2(u64 a, u64 b, u64 c) {
    u64 r;
    asm("fma.rn.f32x2 %0, %1, %2, %3;" : "=l"(r) : "l"(a), "l"(b), "l"(c));
    return r;
}
__device__ __forceinline__ u64 mul2(u64 a, u64 b) {
    u64 r;
    asm("mul.rn.f32x2 %0, %1, %2;" : "=l"(r) : "l"(a), "l"(b));
    return r;
}

__global__ __launch_bounds__(256, 2)
void ssim_main(const float* __restrict__ X, const float* __restrict__ Y,
               float* __restrict__ out, double total, int nblocks) {
    // 11-tap gaussian, sigma=1.5 (torchmetrics default), normalized
    constexpr float G[11] = {
        0.00102838f, 0.00759876f, 0.03600077f, 0.10936069f, 0.21300554f,
        0.26601173f,
        0.21300554f, 0.10936069f, 0.03600077f, 0.00759876f, 0.00102838f
    };
    constexpr float C1 = 1e-4f;   // (0.01*1)^2
    constexpr float C2 = 9e-4f;   // (0.03*1)^2

    // packed coefficients (6 distinct, symmetric)
    u64 G2[6];
    #pragma unroll
    for (int k = 0; k < 6; k++) G2[k] = pk2(G[k], G[k]);
#define GP(k) G2[(k) < 6 ? (k) : 10 - (k)]

    // vertical-blurred rows, even/odd column split, packed (s,d)/(ss,dd)
    __shared__ float2 vPe[4 * HSTR], vPo[4 * HSTR];
    __shared__ float2 vQe[4 * HSTR], vQo[4 * HSTR];
    __shared__ float  red[8];
    __shared__ double dred[256];
    __shared__ bool   amLast;

    const int t   = threadIdx.x;
    const int img = blockIdx.y;
    const int r0  = blockIdx.x * STRIP;
    const int rows = min(STRIP, OW - r0);

    const float* __restrict__ x = X + (size_t)img * IMGPIX + t;
    const float* __restrict__ y = Y + (size_t)img * IMGPIX + t;

    // vertical store target: column t -> half array by parity
    u64* const dstP = (u64*)((t & 1) ? vPo : vPe) + (t >> 1);
    u64* const dstQ = (u64*)((t & 1) ? vQo : vQe) + (t >> 1);

    // horizontal mapping: thread -> (row rr, cols 4g..4g+3)
    const int g  = t & 63;
    const int rr = t >> 6;
    const longlong2* const ePr = (const longlong2*)vPe + rr * (HSTR / 2);
    const longlong2* const oPr = (const longlong2*)vPo + rr * (HSTR / 2);
    const longlong2* const eQr = (const longlong2*)vQe + rr * (HSTR / 2);
    const longlong2* const oQr = (const longlong2*)vQo + rr * (HSTR / 2);

    // register sliding window of packed (s,d), rows o0 .. o0+13
    u64 wP[14];
    #pragma unroll
    for (int i = 0; i < 14; i++) {
        const float xv = x[(r0 + i) * W];
        const float yv = y[(r0 + i) * W];
        wP[i] = pk2(xv + yv, xv - yv);
    }

    float acc = 0.0f;

    for (int g0 = 0; g0 < rows; g0 += 4) {
        const int o0 = r0 + g0;

        // prefetch next group's 4 input rows (clamped)
        float px[4], py[4];
        #pragma unroll
        for (int i = 0; i < 4; i++) {
            const int r = min(o0 + 14 + i, 255);
            px[i] = x[r * W];
            py[i] = y[r * W];
        }

        // squared-channel window (recomputed, not persisted)
        u64 Q[14];
        #pragma unroll
        for (int i = 0; i < 14; i++) Q[i] = mul2(wP[i], wP[i]);

        // ---- vertical blur: all 256 threads, 1 col x 4 rows, packed ----
        #pragma unroll
        for (int j = 0; j < 4; j++) {
            u64 aP = 0ull, aQ = 0ull;
            #pragma unroll
            for (int k = 0; k < 11; k++) {
                aP = fma2(GP(k), wP[j + k], aP);
                aQ = fma2(GP(k), Q[j + k], aQ);
            }
            dstP[j * HSTR] = aP;
            dstQ[j * HSTR] = aQ;
        }
        __syncthreads();

        // ---- horizontal blur + SSIM ----
        const int orow = o0 + rr;
        if (g < 62 && orow < OW) {
            // window of 16 packed columns 4g .. 4g+15, via even/odd LDS.128
            u64 wv[16], wq[16];
            {
                const longlong2 a = ePr[g], b = ePr[g + 1], c = ePr[g + 2], d = ePr[g + 3];
                const longlong2 ao = oPr[g], bo = oPr[g + 1], co = oPr[g + 2], dd = oPr[g + 3];
                wv[0] = a.x;  wv[2] = a.y;  wv[4] = b.x;  wv[6] = b.y;
                wv[8] = c.x;  wv[10] = c.y; wv[12] = d.x; wv[14] = d.y;
                wv[1] = ao.x; wv[3] = ao.y; wv[5] = bo.x; wv[7] = bo.y;
                wv[9] = co.x; wv[11] = co.y; wv[13] = dd.x; wv[15] = dd.y;
            }
            {
                const longlong2 a = eQr[g], b = eQr[g + 1], c = eQr[g + 2], d = eQr[g + 3];
                const longlong2 ao = oQr[g], bo = oQr[g + 1], co = oQr[g + 2], dd = oQr[g + 3];
                wq[0] = a.x;  wq[2] = a.y;  wq[4] = b.x;  wq[6] = b.y;
                wq[8] = c.x;  wq[10] = c.y; wq[12] = d.x; wq[14] = d.y;
                wq[1] = ao.x; wq[3] = ao.y; wq[5] = bo.x; wq[7] = bo.y;
                wq[9] = co.x; wq[11] = co.y; wq[13] = dd.x; wq[15] = dd.y;
            }
            const int c0 = g * 4;
            #pragma unroll
            for (int j = 0; j < 4; j++) {
                u64 mP = 0ull, mQ = 0ull;
                #pragma unroll
                for (int k = 0; k < 11; k++) {
                    mP = fma2(GP(k), wv[j + k], mP);
                    mQ = fma2(GP(k), wq[j + k], mQ);
                }
                if (c0 + j < OW) {
                    float a, b, mss, mdd;
                    upk2(mul2(mP, mP), a, b);   // a = ms^2, b = md^2
                    upk2(mQ, mss, mdd);
                    const float mxmy2  = (a - b) * 0.5f;                    // 2*mx*my
                    const float mx2py2 = (a + b) * 0.5f;                    // mx^2+my^2
                    const float cov2   = (mss - mdd) * 0.5f - mxmy2;        // 2*cov
                    const float varsum = (mss + mdd) * 0.5f - mx2py2;       // vx+vy
                    acc += __fdividef((mxmy2 + C1) * (cov2 + C2),
                                      (mx2py2 + C1) * (varsum + C2));
                }
            }
        }
        __syncthreads();

        // ---- shift window by 4, insert prefetched rows ----
        #pragma unroll
        for (int i = 0; i < 10; i++) wP[i] = wP[i + 4];
        #pragma unroll
        for (int i = 0; i < 4; i++)
            wP[10 + i] = pk2(px[i] + py[i], px[i] - py[i]);
    }

    // ---- block reduction ----
    #pragma unroll
    for (int o = 16; o > 0; o >>= 1)
        acc += __shfl_down_sync(0xffffffffu, acc, o);
    if ((t & 31) == 0) red[t >> 5] = acc;
    __syncthreads();
    if (t == 0) {
        float v = 0.f;
        #pragma unroll
        for (int i = 0; i < 8; i++) v += red[i];
        d_partials[blockIdx.y * NSTRIPS + blockIdx.x] = v;
        __threadfence();
        const int done = atomicAdd(&d_count, 1);
        amLast = (done == nblocks - 1);
    }
    __syncthreads();

    // ---- last block performs the (deterministic, fixed-order) final reduce ----
    if (amLast) {
        double s = 0.0;
        for (int i = t; i < nblocks; i += 256) s += (double)d_partials[i];
        dred[t] = s;
        __syncthreads();
        #pragma unroll
        for (int o = 128; o > 0; o >>= 1) {
            if (t < o) dred[t] += dred[t + o];
            __syncthreads();
        }
        if (t == 0) {
            out[0] = (float)(1.0 - dred[0] / total);
            d_count = 0;   // reset for next graph replay
        }
    }
}

extern "C" void kernel_launch(void* const* d_in, const int* in_sizes, int n_in,
                              void* d_out, int out_size) {
    const float* X = (const float*)d_in[0];
    const float* Y = (const float*)d_in[1];
    const int nimg = in_sizes[0] / IMGPIX;   // 16*31 = 496

    dim3 grid(NSTRIPS, nimg);
    ssim_main<<<grid, 256>>>(X, Y, (float*)d_out,
                             (double)nimg * (double)OW * (double)OW,
                             NSTRIPS * nimg);
}

// round 4
// speedup vs baseline: 1.7643x; 1.7643x over previous
#include <cuda_runtime.h>

#define W       256
#define IMGPIX  65536
#define OW      246
#define STRIP   44
#define NSTRIPS 6

__device__ float d_partials[3072];
__device__ int   d_count = 0;

__global__ __launch_bounds__(256, 3)
void ssim_main(const float* __restrict__ X, const float* __restrict__ Y,
               float* __restrict__ out, double total, int nblocks) {
    // 11-tap gaussian, sigma=1.5 (torchmetrics default), normalized.
    // constexpr taps -> FFMA-imm form in SASS (rt_SMSP = 1, full rate).
    constexpr float G[11] = {
        0.00102838f, 0.00759876f, 0.03600077f, 0.10936069f, 0.21300554f,
        0.26601173f,
        0.21300554f, 0.10936069f, 0.03600077f, 0.00759876f, 0.00102838f
    };
    constexpr float C1 = 1e-4f;   // (0.01*1)^2
    constexpr float C2 = 9e-4f;   // (0.03*1)^2

    __shared__ float v_s [4 * W];   // vertical-blurred rows: 4 rows x 256 cols
    __shared__ float v_d [4 * W];
    __shared__ float v_ss[4 * W];
    __shared__ float v_dd[4 * W];
    __shared__ float red[8];
    __shared__ double dred[256];
    __shared__ bool amLast;

    const int t   = threadIdx.x;
    const int img = blockIdx.y;
    const int r0  = blockIdx.x * STRIP;
    const int rows = min(STRIP, OW - r0);

    const float* __restrict__ x = X + (size_t)img * IMGPIX + t;
    const float* __restrict__ y = Y + (size_t)img * IMGPIX + t;

    // register sliding windows (s, d only): rows o0 .. o0+13 of this column
    float ws[14], wd[14];

    #pragma unroll
    for (int i = 0; i < 14; i++) {
        const float xv = x[(r0 + i) * W];
        const float yv = y[(r0 + i) * W];
        ws[i] = xv + yv;
        wd[i] = xv - yv;
    }

    float acc = 0.0f;
    const int g  = t & 63;   // column group (4 cols) for horizontal phase
    const int rr = t >> 6;   // row within 4-row group

    for (int g0 = 0; g0 < rows; g0 += 4) {
        const int o0 = r0 + g0;   // first output row of this group

        // prefetch next group's 4 input rows (o0+14 .. o0+17), clamped
        float px[4], py[4];
        #pragma unroll
        for (int i = 0; i < 4; i++) {
            const int r = min(o0 + 14 + i, 255);
            px[i] = x[r * W];
            py[i] = y[r * W];
        }

        // squared channels for this iteration (recomputed, not persisted)
        float qs[14], qd[14];
        #pragma unroll
        for (int i = 0; i < 14; i++) { qs[i] = ws[i] * ws[i]; qd[i] = wd[i] * wd[i]; }

        // ---- vertical blur (all 256 threads, 1 col x 4 rows x 4 ch) ----
        #pragma unroll
        for (int j = 0; j < 4; j++) {
            float as = 0.f, ad = 0.f, ass = 0.f, add = 0.f;
            #pragma unroll
            for (int k = 0; k < 11; k++) {
                as  = fmaf(G[k], ws[j + k], as);
                ad  = fmaf(G[k], wd[j + k], ad);
                ass = fmaf(G[k], qs[j + k], ass);
                add = fmaf(G[k], qd[j + k], add);
            }
            v_s [j * W + t] = as;
            v_d [j * W + t] = ad;
            v_ss[j * W + t] = ass;
            v_dd[j * W + t] = add;
        }
        __syncthreads();

        // ---- horizontal blur + SSIM: thread -> (row rr, cols 4g..4g+3) ----
        const int orow = o0 + rr;
        if (g < 62 && orow < OW) {
            float ms[4], md[4], mss[4], mdd[4];
#define HPASS(VB, OUT)                                                         \
            {                                                                  \
                const float4* vp = (const float4*)(VB) + rr * 64 + g;          \
                const float4 A = vp[0], B = vp[1], Cc = vp[2], D = vp[3];      \
                const float w[16] = {A.x, A.y, A.z, A.w, B.x, B.y, B.z, B.w,   \
                                     Cc.x, Cc.y, Cc.z, Cc.w, D.x, D.y, D.z, D.w}; \
                _Pragma("unroll")                                              \
                for (int j = 0; j < 4; j++) {                                  \
                    float sv = 0.0f;                                           \
                    _Pragma("unroll")                                          \
                    for (int k = 0; k < 11; k++)                               \
                        sv = fmaf(G[k], w[j + k], sv);                         \
                    OUT[j] = sv;                                               \
                }                                                              \
            }
            HPASS(v_s,  ms)
            HPASS(v_d,  md)
            HPASS(v_ss, mss)
            HPASS(v_dd, mdd)
#undef HPASS
            const int c0 = g * 4;
            #pragma unroll
            for (int j = 0; j < 4; j++) {
                if (c0 + j < OW) {
                    const float a = ms[j] * ms[j];
                    const float b = md[j] * md[j];
                    const float mxmy2  = (a - b) * 0.5f;                    // 2*mx*my
                    const float mx2py2 = (a + b) * 0.5f;                    // mx^2+my^2
                    const float cov2   = (mss[j] - mdd[j]) * 0.5f - mxmy2;  // 2*cov
                    const float varsum = (mss[j] + mdd[j]) * 0.5f - mx2py2; // vx+vy
                    acc += __fdividef((mxmy2 + C1) * (cov2 + C2),
                                      (mx2py2 + C1) * (varsum + C2));
                }
            }
        }
        __syncthreads();

        // ---- shift windows by 4, insert prefetched rows ----
        #pragma unroll
        for (int i = 0; i < 10; i++) { ws[i] = ws[i + 4]; wd[i] = wd[i + 4]; }
        #pragma unroll
        for (int i = 0; i < 4; i++) {
            ws[10 + i] = px[i] + py[i];
            wd[10 + i] = px[i] - py[i];
        }
    }

    // ---- block reduction ----
    #pragma unroll
    for (int o = 16; o > 0; o >>= 1)
        acc += __shfl_down_sync(0xffffffffu, acc, o);
    if ((t & 31) == 0) red[t >> 5] = acc;
    __syncthreads();
    if (t == 0) {
        float v = 0.f;
        #pragma unroll
        for (int i = 0; i < 8; i++) v += red[i];
        d_partials[blockIdx.y * NSTRIPS + blockIdx.x] = v;
        __threadfence();
        const int done = atomicAdd(&d_count, 1);
        amLast = (done == nblocks - 1);
    }
    __syncthreads();

    // ---- last block performs the deterministic fixed-order final reduce ----
    if (amLast) {
        double s = 0.0;
        for (int i = t; i < nblocks; i += 256) s += (double)d_partials[i];
        dred[t] = s;
        __syncthreads();
        #pragma unroll
        for (int o = 128; o > 0; o >>= 1) {
            if (t < o) dred[t] += dred[t + o];
            __syncthreads();
        }
        if (t == 0) {
            out[0] = (float)(1.0 - dred[0] / total);
            d_count = 0;   // reset for next graph replay
        }
    }
}

extern "C" void kernel_launch(void* const* d_in, const int* in_sizes, int n_in,
                              void* d_out, int out_size) {
    const float* X = (const float*)d_in[0];
    const float* Y = (const float*)d_in[1];
    const int nimg = in_sizes[0] / IMGPIX;   // 16*31 = 496

    dim3 grid(NSTRIPS, nimg);
    ssim_main<<<grid, 256>>>(X, Y, (float*)d_out,
                             (double)nimg * (double)OW * (double)OW,
                             NSTRIPS * nimg);
}